// round 10
// baseline (speedup 1.0000x reference)
#include <cuda_runtime.h>

#define T 4
#define H 128
#define W 128
#define NCI 16
#define NCIN 64
#define PS 7
#define WSZ 27
#define NQ 1024
#define KSEL 100
#define PITCHP 35      // region pitch (in float2 units)
#define CHP 1225       // 35*35 float2 per channel
#define PD 784         // NCI*PS*PS

__device__ float v1g[T * NCI * H * W];
__device__ float v2g[T * NCI * H * W];
__device__ float zbuf[T * NQ * PD];

// packed fp32x2 FMA: acc.{lo,hi} += a.{lo,hi} * b.{lo,hi}
#define FMA2(acc, a, b) \
    asm("fma.rn.f32x2 %0, %1, %2, %0;" : "+l"(acc) : "l"(a), "l"(b))

// ---------------------------------------------------------------------------
// Kernel 0: no-op (capture-slot alignment: index 15 -> main_kernel)
// ---------------------------------------------------------------------------
__global__ void nudge_kernel() {}

// ---------------------------------------------------------------------------
// Kernel 1: fused 3x3 conv (v1) + 1x1 conv (v2), 64ch -> 16ch
// ---------------------------------------------------------------------------
__global__ void __launch_bounds__(128) conv_kernel(
    const float* __restrict__ vid, const float* __restrict__ gw,
    const float* __restrict__ gb, const float* __restrict__ thw,
    const float* __restrict__ thb)
{
    extern __shared__ float sm[];
    float* wsm  = sm;              // [64][9][16] = 9216 f
    float* thsm = sm + 9216;       // [64][16]    = 1024 f
    float* tsm  = sm + 10240;      // [8][18][10] = 1440 f

    int tid = threadIdx.x;
    int t = blockIdx.y;
    int bx = blockIdx.x;
    int ty0 = (bx >> 4) * 16, tx0 = (bx & 15) * 8;

    for (int n = tid; n < NCI * NCIN * 9; n += 128) {
        int co = n / 576, r = n - co * 576;
        int cin = r / 9, k = r - cin * 9;
        wsm[(cin * 9 + k) * 16 + co] = gw[n];
    }
    for (int n = tid; n < NCI * NCIN; n += 128) {
        int co = n >> 6, cin = n & 63;
        thsm[cin * 16 + co] = thw[co * 64 + cin];
    }

    float acc1[16], acc2[16];
#pragma unroll
    for (int i = 0; i < 16; i++) { acc1[i] = 0.f; acc2[i] = 0.f; }

    int py = tid >> 3, px = tid & 7;
    int gy = ty0 + py, gx = tx0 + px;

    for (int c0 = 0; c0 < NCIN; c0 += 8) {
        __syncthreads();
        for (int n = tid; n < 8 * 18 * 10; n += 128) {
            int cc = n / 180, r = n - cc * 180;
            int yy = r / 10, xx = r - yy * 10;
            int iy = ty0 + yy - 1, ix = tx0 + xx - 1;
            float v = 0.f;
            if (iy >= 0 && iy < H && ix >= 0 && ix < W)
                v = vid[((t * NCIN + c0 + cc) * H + iy) * W + ix];
            tsm[n] = v;
        }
        __syncthreads();
#pragma unroll
        for (int cc = 0; cc < 8; cc++) {
            const float* tp = &tsm[cc * 180 + py * 10 + px];
            float v[9];
            v[0] = tp[0];  v[1] = tp[1];  v[2] = tp[2];
            v[3] = tp[10]; v[4] = tp[11]; v[5] = tp[12];
            v[6] = tp[20]; v[7] = tp[21]; v[8] = tp[22];
            const float4* wp = reinterpret_cast<const float4*>(&wsm[(c0 + cc) * 144]);
#pragma unroll
            for (int k = 0; k < 9; k++) {
                float vv = v[k];
#pragma unroll
                for (int q4 = 0; q4 < 4; q4++) {
                    float4 w4 = wp[k * 4 + q4];
                    acc1[q4 * 4 + 0] += vv * w4.x;
                    acc1[q4 * 4 + 1] += vv * w4.y;
                    acc1[q4 * 4 + 2] += vv * w4.z;
                    acc1[q4 * 4 + 3] += vv * w4.w;
                }
            }
            float vc = v[4];
            const float4* tp4 = reinterpret_cast<const float4*>(&thsm[(c0 + cc) * 16]);
#pragma unroll
            for (int q4 = 0; q4 < 4; q4++) {
                float4 w4 = tp4[q4];
                acc2[q4 * 4 + 0] += vc * w4.x;
                acc2[q4 * 4 + 1] += vc * w4.y;
                acc2[q4 * 4 + 2] += vc * w4.z;
                acc2[q4 * 4 + 3] += vc * w4.w;
            }
        }
    }
#pragma unroll
    for (int co = 0; co < 16; co++) {
        int oidx = ((t * NCI + co) * H + gy) * W + gx;
        v1g[oidx] = acc1[co] + gb[co];
        v2g[oidx] = acc2[co] + thb[co];
    }
}

// ---------------------------------------------------------------------------
// Kernel 2: packed-f32x2 score loop. 3x4 window tiles (12/thread), 63 tiles x
// 4 channel-slices = 252 threads; 4 staging passes of 4 channels.
// Region staged as x-overlapping pairs regP[y][x] = {v[x], v[x+1]};
// query staged duplicated qpd = {q,q}. All window MACs are fma.rn.f32x2.
// Band select (sort-free common path) + bitonic fallback as before.
// smem (floats):
//   regP : 0     .. 9800   (4ch x 35 x 35 float2)
//   qpd  : 9800  .. 10192  (4ch x 49 float2)   [wgt/cyx/redf/nzc/nzi alias]
//   sc   : 10192 .. 10921  (729)
// aliases over regP after score: partials [3][63][12]; keys (fallback).
// ---------------------------------------------------------------------------
#define SMF 10924

__device__ __forceinline__ void stage4p(
    const float* __restrict__ src, float2* __restrict__ regP,
    int r0, int c0, int w5, int lane)
{
    int xa1 = min(c0 + lane, 127),      xb1 = min(c0 + lane + 1, 127);
    int xa2 = min(c0 + 32 + lane, 127), xb2 = min(c0 + 33 + lane, 127);
#pragma unroll
    for (int ci = 0; ci < 4; ci++) {
        const float* sb = src + ci * (H * W);
        float2* db = regP + ci * CHP;
#pragma unroll 2
        for (int y = w5; y < PITCHP; y += 8) {
            const float* srow = sb + min(r0 + y, 127) * W;
            float2* drow = db + y * PITCHP;
            drow[lane] = make_float2(srow[xa1], srow[xb1]);
            if (lane < 3) drow[32 + lane] = make_float2(srow[xa2], srow[xb2]);
        }
    }
}

__global__ void __launch_bounds__(256, 4) main_kernel()
{
    extern __shared__ float sm[];
    float2* regP = reinterpret_cast<float2*>(sm);              // 4900 f2
    unsigned long long* regPu = reinterpret_cast<unsigned long long*>(sm);
    float2* qpd = reinterpret_cast<float2*>(sm + 9800);        // 196 f2
    unsigned long long* qpdu = reinterpret_cast<unsigned long long*>(sm + 9800);
    float* sc = sm + 10192;                                    // 729
    // aliases:
    float* partials = sm;                                      // [3][63][12]
    unsigned long long* keys = (unsigned long long*)sm;        // fallback only
    float* wgt  = sm + 9800;                                   // 100
    int*   cyx  = (int*)(sm + 9900);                           // 100
    float* redf = sm + 10000;                                  // 8
    int*   nzc  = (int*)(sm + 10008);                          // 1
    int*   nzi  = (int*)(sm + 10012);                          // 100

    int tid = threadIdx.x;
    int w5 = tid >> 5, lane = tid & 31;
    int q = blockIdx.x, t = blockIdx.y;
    int qi = (q >> 5) << 2, qj = (q & 31) << 2;
    int r0 = max(qi - 13, 0);
    int c0 = max(qj - 13, 0);

    // thread -> (channel slice, 3x4 candidate tile)
    bool act = tid < 252;
    int slice = 0, tile = 0;
    if (act) { slice = tid / 63; tile = tid - slice * 63; }
    int ty = tile % 9, tx = tile / 9;
    int oy0 = ty * 3, ox0 = tx * 4;
    int ay0 = max(qi + oy0 - 13 - r0, 0);
    int ax0 = max(qj + ox0 - 13 - c0, 0);
    int ey1 = max(qi + oy0 - 12 - r0, 0) - ay0;
    int ey2 = max(qi + oy0 - 11 - r0, 0) - ay0;
    int ex1 = max(qj + ox0 - 12 - c0, 0) - ax0;
    int ex2 = max(qj + ox0 - 11 - c0, 0) - ax0;
    int ex3 = max(qj + ox0 - 10 - c0, 0) - ax0;

    // qpd builder mapping (fixed across passes)
    int qci = tid / 49, qrr = tid % 49;
    int qpi = qrr / 7, qpj = qrr - qpi * 7;
    int qsrc = qci * CHP + (qi - r0 + qpi) * PITCHP + (qj - c0 + qpj);

    // 12 window accumulators as 6 packed f32x2: [e*2+0]={s0,s1}, [e*2+1]={s2,s3}
    unsigned long long w2[6];
#pragma unroll
    for (int k = 0; k < 6; k++) w2[k] = 0ull;

#pragma unroll 1
    for (int pass = 0; pass < 4; pass++) {
        stage4p(v1g + (t * NCI + pass * 4) * H * W, regP, r0, c0, w5, lane);
        __syncthreads();

        if (tid < 196) {
            float qv = regP[qsrc].x;
            qpd[tid] = make_float2(qv, qv);
        }
        __syncthreads();

        if (act) {
            const unsigned long long* base =
                regPu + slice * CHP + ay0 * PITCHP + ax0;
            const unsigned long long* qb = qpdu + slice * 49;
#pragma unroll
            for (int r = 0; r < 9; r++) {
                unsigned long long p[9];
#pragma unroll
                for (int j = 0; j < 9; j++) p[j] = base[r * PITCHP + j];
#pragma unroll
                for (int e = 0; e < 3; e++) {
                    int pi = r - e;
                    if (pi >= 0 && pi < 7) {
                        const unsigned long long* qrow = qb + pi * 7;
#pragma unroll
                        for (int pj = 0; pj < 7; pj++) {
                            unsigned long long qq = qrow[pj];
                            FMA2(w2[e * 2 + 0], qq, p[pj]);
                            FMA2(w2[e * 2 + 1], qq, p[pj + 2]);
                        }
                    }
                }
            }
        }
        __syncthreads();   // before restage / partial writes overwrite regP
    }

    // ---- cross-slice reduction via regP alias ----
    if (act && slice > 0) {
        float* pp = partials + ((slice - 1) * 63 + tile) * 12;
#pragma unroll
        for (int k = 0; k < 6; k++) {
            pp[2 * k]     = __uint_as_float((unsigned)(w2[k] & 0xFFFFFFFFull));
            pp[2 * k + 1] = __uint_as_float((unsigned)(w2[k] >> 32));
        }
    }
    __syncthreads();
    float m3 = -3.4e38f;
    if (tid < 63) {
        float wv[12];
#pragma unroll
        for (int k = 0; k < 6; k++) {
            wv[2 * k]     = __uint_as_float((unsigned)(w2[k] & 0xFFFFFFFFull));
            wv[2 * k + 1] = __uint_as_float((unsigned)(w2[k] >> 32));
        }
#pragma unroll
        for (int s = 0; s < 3; s++) {
            const float* pp = partials + (s * 63 + tile) * 12;
#pragma unroll
            for (int k = 0; k < 12; k++) wv[k] += pp[k];
        }
        // emit candidates with clamp-window selection
#pragma unroll
        for (int dy = 0; dy < 3; dy++) {
            int e = (dy == 0) ? 0 : ((dy == 1) ? ey1 : ey2);
            float a0 = (e == 0) ? wv[0] : ((e == 1) ? wv[4] : wv[8]);
            float a1 = (e == 0) ? wv[1] : ((e == 1) ? wv[5] : wv[9]);
            float a2 = (e == 0) ? wv[2] : ((e == 1) ? wv[6] : wv[10]);
            float a3 = (e == 0) ? wv[3] : ((e == 1) ? wv[7] : wv[11]);
            int o = (oy0 + dy) * WSZ + ox0;
            float s0 = a0;
            float s1 = (ex1 == 0) ? a0 : ((ex1 == 1) ? a1 : ((ex1 == 2) ? a2 : a3));
            float s2 = (ex2 == 0) ? a0 : ((ex2 == 1) ? a1 : ((ex2 == 2) ? a2 : a3));
            float s3 = (ex3 == 0) ? a0 : ((ex3 == 1) ? a1 : ((ex3 == 2) ? a2 : a3));
            sc[o] = s0;
            sc[o + 1] = s1;
            sc[o + 2] = s2;
            m3 = fmaxf(m3, fmaxf(s0, fmaxf(s1, s2)));
            if (ox0 + 3 < WSZ) {
                sc[o + 3] = s3;
                m3 = fmaxf(m3, s3);
            }
        }
    }
    // ---- exact block max ----
#pragma unroll
    for (int s = 16; s > 0; s >>= 1) m3 = fmaxf(m3, __shfl_xor_sync(0xffffffffu, m3, s));
    if (lane == 0) redf[w5] = m3;
    __syncthreads();
    float vmax = redf[0];
#pragma unroll
    for (int s = 1; s < 8; s++) vmax = fmaxf(vmax, redf[s]);
    float th = vmax - 12.0f;

    // ---- band compaction (warp 0) ----
    if (tid < 32) {
        int cnt = 0;
        for (int base = 0; base < 736; base += 32) {
            int i = base + tid;
            bool f = (i < WSZ * WSZ) && (sc[i] >= th);
            unsigned m = __ballot_sync(0xffffffffu, f);
            int pos = cnt + __popc(m & ((1u << tid) - 1u));
            if (f && pos < KSEL) nzi[pos] = i;
            cnt += __popc(m);
        }
        if (tid == 0) *nzc = cnt;
    }
    __syncthreads();
    int bandcnt = *nzc;

    int nnz;
    float inv;
    if (bandcnt <= KSEL) {
        nnz = bandcnt;
        float e = 0.f;
        if (tid < nnz) {
            int csel = nzi[tid];
            int soy = csel / WSZ, sox = csel - soy * WSZ;
            int cy = min(max(qi + soy - 13, 0), H - 1);
            int cx = min(max(qj + sox - 13, 0), W - 1);
            cyx[tid] = (cy << 16) | cx;
            e = expf((sc[csel] - vmax) * 10.f);
            wgt[tid] = e;
        }
#pragma unroll
        for (int s = 16; s > 0; s >>= 1) e += __shfl_xor_sync(0xffffffffu, e, s);
        if (lane == 0) redf[w5] = e;
        __syncthreads();
        inv = 1.f / (redf[0] + redf[1] + redf[2] + redf[3]
                   + redf[4] + redf[5] + redf[6] + redf[7]);
        __syncthreads();
    } else {
        // ---- fallback: exact top-100 via full bitonic sort (rare) ----
        for (int i = tid; i < 1024; i += 256) {
            unsigned long long kk;
            if (i < WSZ * WSZ) {
                unsigned int b = __float_as_uint(sc[i]);
                unsigned int u = (b & 0x80000000u) ? ~b : (b | 0x80000000u);
                kk = (((unsigned long long)(~u)) << 32) | (unsigned int)i;
            } else {
                kk = 0xFFFFFFFFFFFFFFFFull;
            }
            keys[i] = kk;
        }
        __syncthreads();
#pragma unroll 1
        for (int k = 2; k <= 1024; k <<= 1) {
#pragma unroll 1
            for (int j = k >> 1; j > 0; j >>= 1) {
                if (j >= 128) {
                    __syncthreads();
                    for (int i = tid; i < 1024; i += 256) {
                        int ixj = i ^ j;
                        if (ixj > i) {
                            bool up = ((i & k) == 0);
                            unsigned long long a = keys[i], b = keys[ixj];
                            if ((a > b) == up) { keys[i] = b; keys[ixj] = a; }
                        }
                    }
                    __syncthreads();
                } else {
#pragma unroll
                    for (int n = 0; n < 4; n++) {
                        int i = (w5 << 7) + (n << 5) + lane;
                        int ixj = i ^ j;
                        if (ixj > i) {
                            bool up = ((i & k) == 0);
                            unsigned long long a = keys[i], b = keys[ixj];
                            if ((a > b) == up) { keys[i] = b; keys[ixj] = a; }
                        }
                    }
                    __syncwarp();
                }
            }
        }
        __syncthreads();
        nnz = KSEL;
        float e = 0.f;
        if (tid < KSEL) {
            int csel = (int)(keys[tid] & 0xFFFFFFFFull);
            int soy = csel / WSZ, sox = csel - soy * WSZ;
            int cy = min(max(qi + soy - 13, 0), H - 1);
            int cx = min(max(qj + sox - 13, 0), W - 1);
            cyx[tid] = (cy << 16) | cx;
            e = expf((sc[csel] - vmax) * 10.f);
            wgt[tid] = e;
        }
#pragma unroll
        for (int s = 16; s > 0; s >>= 1) e += __shfl_xor_sync(0xffffffffu, e, s);
        if (lane == 0) redf[w5] = e;
        __syncthreads();
        inv = 1.f / (redf[0] + redf[1] + redf[2] + redf[3]
                   + redf[4] + redf[5] + redf[6] + redf[7]);
        __syncthreads();
    }

    // ---- aggregation: 4 d's per thread, MLP-4 L2 loads from v2 ----
    const float* v2t = v2g + t * NCI * H * W;
    float* zp = zbuf + (t * NQ + q) * PD;
    if (tid < 196) {
        int d0 = tid * 4;
        int cb[4], piu[4], pju[4];
#pragma unroll
        for (int u = 0; u < 4; u++) {
            int d = d0 + u;
            int ci = d / 49, r = d - ci * 49;
            piu[u] = r / 7; pju[u] = r - piu[u] * 7;
            cb[u] = ci * (H * W);
        }
        float acc[4] = {0.f, 0.f, 0.f, 0.f};
#pragma unroll 1
        for (int m = 0; m < nnz; m++) {
            float wv = wgt[m];
            if (wv == 0.f) continue;
            int p = cyx[m];
            int cy = p >> 16, cx = p & 0xFFFF;
#pragma unroll
            for (int u = 0; u < 4; u++) {
                int ryv = min(cy + piu[u], H - 1);
                int rxv = min(cx + pju[u], W - 1);
                acc[u] += wv * v2t[cb[u] + ryv * W + rxv];
            }
        }
#pragma unroll
        for (int u = 0; u < 4; u++) zp[d0 + u] = acc[u] * inv;
    }
}

// ---------------------------------------------------------------------------
// Kernel 3: deterministic overlap-add gather + normalize by Zc
// ---------------------------------------------------------------------------
__global__ void __launch_bounds__(256) final_kernel(float* __restrict__ out)
{
    int idx = blockIdx.x * 256 + threadIdx.x;
    if (idx >= T * NCI * H * W) return;
    int x = idx & 127;
    int y = (idx >> 7) & 127;
    int ci = (idx >> 14) & 15;
    int t = idx >> 18;

    int ai[4], api[4], ni = 0;
    if (y == 127) {
        ai[0] = ai[1] = ai[2] = ai[3] = 31;
        api[0] = 3; api[1] = 4; api[2] = 5; api[3] = 6; ni = 4;
    } else {
        for (int p = (y & 3); p < 7; p += 4) {
            int a = (y - p) >> 2;
            if (y - p >= 0) { ai[ni] = a; api[ni] = p; ni++; }
        }
    }
    int aj[4], apj[4], nj = 0;
    if (x == 127) {
        aj[0] = aj[1] = aj[2] = aj[3] = 31;
        apj[0] = 3; apj[1] = 4; apj[2] = 5; apj[3] = 6; nj = 4;
    } else {
        for (int p = (x & 3); p < 7; p += 4) {
            int a = (x - p) >> 2;
            if (x - p >= 0) { aj[nj] = a; apj[nj] = p; nj++; }
        }
    }

    float acc = 0.f;
    for (int u = 0; u < ni; u++) {
        for (int v = 0; v < nj; v++) {
            int qq = ai[u] * 32 + aj[v];
            int d = ci * 49 + api[u] * 7 + apj[v];
            acc += zbuf[((t << 10) + qq) * PD + d];
        }
    }
    out[idx] = acc / (float)(ni * nj);
}

// ---------------------------------------------------------------------------
extern "C" void kernel_launch(void* const* d_in, const int* in_sizes, int n_in,
                              void* d_out, int out_size)
{
    const float* vid = (const float*)d_in[0];
    const float* gw  = (const float*)d_in[1];
    const float* gb  = (const float*)d_in[2];
    const float* thw = (const float*)d_in[3];
    const float* thb = (const float*)d_in[4];
    float* out = (float*)d_out;

    int conv_sm = (9216 + 1024 + 1440) * 4;   // 46720 B
    int main_sm = SMF * 4;                     // 43696 B
    cudaFuncSetAttribute(conv_kernel, cudaFuncAttributeMaxDynamicSharedMemorySize, conv_sm);
    cudaFuncSetAttribute(main_kernel, cudaFuncAttributeMaxDynamicSharedMemorySize, main_sm);

    nudge_kernel<<<1, 32>>>();                                   // idx 0 (mod 6)
    conv_kernel<<<dim3(128, T), 128, conv_sm>>>(vid, gw, gb, thw, thb);  // idx 1
    nudge_kernel<<<1, 32>>>();                                   // idx 2
    main_kernel<<<dim3(NQ, T), 256, main_sm>>>();                // idx 3  <- ncu slot 15
    int ntot = T * NCI * H * W;
    final_kernel<<<(ntot + 255) / 256, 256>>>(out);              // idx 4
    nudge_kernel<<<1, 32>>>();                                   // idx 5
}

// round 13
// speedup vs baseline: 1.0883x; 1.0883x over previous
#include <cuda_runtime.h>

#define T 4
#define H 128
#define W 128
#define NCI 16
#define NCIN 64
#define PS 7
#define WSZ 27
#define NQ 1024
#define KSEL 100
#define PITCH2 33
#define CHSZ 1089   // 33*33
#define PD 784      // NCI*PS*PS

__device__ float v1g[T * NCI * H * W];
__device__ float v2g[T * NCI * H * W];
__device__ float zbuf[T * NQ * PD];

// ---------------------------------------------------------------------------
// Kernel 0: no-op (capture-slot alignment: index 15 -> main_kernel)
// ---------------------------------------------------------------------------
__global__ void nudge_kernel() {}

// ---------------------------------------------------------------------------
// Kernel 1: fused 3x3 conv (v1) + 1x1 conv (v2), 64ch -> 16ch
// ---------------------------------------------------------------------------
__global__ void __launch_bounds__(128) conv_kernel(
    const float* __restrict__ vid, const float* __restrict__ gw,
    const float* __restrict__ gb, const float* __restrict__ thw,
    const float* __restrict__ thb)
{
    extern __shared__ float sm[];
    float* wsm  = sm;              // [64][9][16] = 9216 f
    float* thsm = sm + 9216;       // [64][16]    = 1024 f
    float* tsm  = sm + 10240;      // [8][18][10] = 1440 f

    int tid = threadIdx.x;
    int t = blockIdx.y;
    int bx = blockIdx.x;
    int ty0 = (bx >> 4) * 16, tx0 = (bx & 15) * 8;

    for (int n = tid; n < NCI * NCIN * 9; n += 128) {
        int co = n / 576, r = n - co * 576;
        int cin = r / 9, k = r - cin * 9;
        wsm[(cin * 9 + k) * 16 + co] = gw[n];
    }
    for (int n = tid; n < NCI * NCIN; n += 128) {
        int co = n >> 6, cin = n & 63;
        thsm[cin * 16 + co] = thw[co * 64 + cin];
    }

    float acc1[16], acc2[16];
#pragma unroll
    for (int i = 0; i < 16; i++) { acc1[i] = 0.f; acc2[i] = 0.f; }

    int py = tid >> 3, px = tid & 7;
    int gy = ty0 + py, gx = tx0 + px;

    for (int c0 = 0; c0 < NCIN; c0 += 8) {
        __syncthreads();
        for (int n = tid; n < 8 * 18 * 10; n += 128) {
            int cc = n / 180, r = n - cc * 180;
            int yy = r / 10, xx = r - yy * 10;
            int iy = ty0 + yy - 1, ix = tx0 + xx - 1;
            float v = 0.f;
            if (iy >= 0 && iy < H && ix >= 0 && ix < W)
                v = vid[((t * NCIN + c0 + cc) * H + iy) * W + ix];
            tsm[n] = v;
        }
        __syncthreads();
#pragma unroll
        for (int cc = 0; cc < 8; cc++) {
            const float* tp = &tsm[cc * 180 + py * 10 + px];
            float v[9];
            v[0] = tp[0];  v[1] = tp[1];  v[2] = tp[2];
            v[3] = tp[10]; v[4] = tp[11]; v[5] = tp[12];
            v[6] = tp[20]; v[7] = tp[21]; v[8] = tp[22];
            const float4* wp = reinterpret_cast<const float4*>(&wsm[(c0 + cc) * 144]);
#pragma unroll
            for (int k = 0; k < 9; k++) {
                float vv = v[k];
#pragma unroll
                for (int q4 = 0; q4 < 4; q4++) {
                    float4 w4 = wp[k * 4 + q4];
                    acc1[q4 * 4 + 0] += vv * w4.x;
                    acc1[q4 * 4 + 1] += vv * w4.y;
                    acc1[q4 * 4 + 2] += vv * w4.z;
                    acc1[q4 * 4 + 3] += vv * w4.w;
                }
            }
            float vc = v[4];
            const float4* tp4 = reinterpret_cast<const float4*>(&thsm[(c0 + cc) * 16]);
#pragma unroll
            for (int q4 = 0; q4 < 4; q4++) {
                float4 w4 = tp4[q4];
                acc2[q4 * 4 + 0] += vc * w4.x;
                acc2[q4 * 4 + 1] += vc * w4.y;
                acc2[q4 * 4 + 2] += vc * w4.z;
                acc2[q4 * 4 + 3] += vc * w4.w;
            }
        }
    }
#pragma unroll
    for (int co = 0; co < 16; co++) {
        int oidx = ((t * NCI + co) * H + gy) * W + gx;
        v1g[oidx] = acc1[co] + gb[co];
        v2g[oidx] = acc2[co] + thb[co];
    }
}

// ---------------------------------------------------------------------------
// Kernel 2: 3x3 candidate tiles x 3 channel-slices, clamped 33x33 staging,
// band select (sort-free common path, bitonic fallback). qp built from gmem
// in the staging phase (one barrier per pass saved).
// smem (floats): reg 0..8712 | qp 8712..9168 | sc 9168..9897
// aliases after score: partials+keys over reg; wgt/... over qp.
// ---------------------------------------------------------------------------
#define SMF 9897

__device__ __forceinline__ void stage8c(
    const float* __restrict__ src, float* __restrict__ reg,
    int r0, int c0, int w5, int lane)
{
    int xs1 = min(c0 + lane, 127);
    int xs2 = min(c0 + 32, 127);
#pragma unroll
    for (int ci = 0; ci < 8; ci++) {
        const float* sbase = src + ci * (H * W);
        float* dbase = reg + ci * CHSZ;
#pragma unroll 2
        for (int y = w5; y < PITCH2; y += 8) {
            const float* srow = sbase + min(r0 + y, 127) * W;
            float* drow = dbase + y * PITCH2;
            drow[lane] = srow[xs1];
            if (lane == 0) drow[32] = srow[xs2];
        }
    }
}

__global__ void __launch_bounds__(256, 4) main_kernel()
{
    extern __shared__ float sm[];
    float* reg = sm;
    float* qp  = sm + 8712;
    float* sc  = sm + 9168;
    // aliases (live only after score phase):
    float* partials = sm;                                 // [2][81][9] over reg
    unsigned long long* keys = (unsigned long long*)sm;   // fallback only
    float* wgt  = (float*)(qp);                           // 100
    int*   cyx  = (int*)(qp + 100);                       // 100 (abs cy<<16|cx)
    float* redf = qp + 200;                               // 8
    int*   nzc  = (int*)(qp + 216);                       // 1
    int*   nzi  = (int*)(qp + 220);                       // 100

    int tid = threadIdx.x;
    int w5 = tid >> 5, lane = tid & 31;
    int q = blockIdx.x, t = blockIdx.y;
    int qi = (q >> 5) << 2, qj = (q & 31) << 2;
    int r0 = max(qi - 13, 0);
    int c0 = max(qj - 13, 0);

    // thread -> (channel slice, 3x3 candidate tile)
    bool act = tid < 243;
    int slice = 0, tile = 0;
    if (act) { slice = tid / 81; tile = tid - slice * 81; }
    int ty = tile % 9, tx = tile / 9;
    int oy0 = ty * 3, ox0 = tx * 3;
    // clamped anchors (upper clamp baked into staging; lower via e-offsets)
    int ay0 = max(qi + oy0 - 13 - r0, 0);
    int ax0 = max(qj + ox0 - 13 - c0, 0);
    int ey1 = max(qi + oy0 - 12 - r0, 0) - ay0;
    int ey2 = max(qi + oy0 - 11 - r0, 0) - ay0;
    int ex1 = max(qj + ox0 - 12 - c0, 0) - ax0;
    int ex2 = max(qj + ox0 - 11 - c0, 0) - ax0;
    int cs = slice * 3;
    int ce = (slice == 2) ? 8 : cs + 3;

    // qp-build mapping: threads 0..195 each write d = tid and d = tid+196
    const float* v1t = v1g + t * NCI * H * W;
    int qd0 = tid, qd1 = tid + 196;
    int qci0 = qd0 / 49, qr0q = qd0 - qci0 * 49;
    int qpi0 = qr0q / 7, qpj0 = qr0q - qpi0 * 7;
    int qci1 = qd1 / 49, qr1q = qd1 - qci1 * 49;
    int qpi1 = qr1q / 7, qpj1 = qr1q - qpi1 * 7;
    int qsrc0 = (min(qi + qpi0, 127)) * W + min(qj + qpj0, 127);
    int qsrc1 = (min(qi + qpi1, 127)) * W + min(qj + qpj1, 127);

    float w[9];
#pragma unroll
    for (int k = 0; k < 9; k++) w[k] = 0.f;

#pragma unroll 1
    for (int pass = 0; pass < 2; pass++) {
        const float* v1p = v1t + pass * 8 * H * W;
        stage8c(v1p, reg, r0, c0, w5, lane);
        // qp built directly from gmem (L2) in the same phase
        if (tid < 196) {
            qp[(qci0 * 7 + qpi0) * 8 + qpj0] = v1p[qci0 * (H * W) + qsrc0];
            qp[(qci1 * 7 + qpi1) * 8 + qpj1] = v1p[qci1 * (H * W) + qsrc1];
        }
        __syncthreads();

        if (act) {
#pragma unroll 1
            for (int ci = cs; ci < ce; ci++) {
                const float* base = reg + ci * CHSZ + ay0 * PITCH2 + ax0;
                const float4* qv = reinterpret_cast<const float4*>(qp) + ci * 14;
#pragma unroll
                for (int r = 0; r < 9; r++) {
                    const float* row = base + r * PITCH2;
                    float v0 = row[0], v1 = row[1], v2 = row[2], v3 = row[3];
                    float v4 = row[4], v5 = row[5], v6 = row[6], v7 = row[7];
                    float v8 = row[8];
#pragma unroll
                    for (int e = 0; e < 3; e++) {
                        int pi = r - e;
                        if (pi >= 0 && pi < 7) {
                            float4 a = qv[2 * pi], b = qv[2 * pi + 1];
                            w[e * 3 + 0] += a.x * v0 + a.y * v1 + a.z * v2 + a.w * v3
                                          + b.x * v4 + b.y * v5 + b.z * v6;
                            w[e * 3 + 1] += a.x * v1 + a.y * v2 + a.z * v3 + a.w * v4
                                          + b.x * v5 + b.y * v6 + b.z * v7;
                            w[e * 3 + 2] += a.x * v2 + a.y * v3 + a.z * v4 + a.w * v5
                                          + b.x * v6 + b.y * v7 + b.z * v8;
                        }
                    }
                }
            }
        }
        __syncthreads();   // before restage / partial writes overwrite reg
    }

    // ---- cross-slice reduction via reg alias ----
    if (act && slice > 0) {
        float* pp = partials + ((slice - 1) * 81 + tile) * 9;
#pragma unroll
        for (int k = 0; k < 9; k++) pp[k] = w[k];
    }
    __syncthreads();
    float m3 = -3.4e38f;
    if (tid < 81) {
        const float* p1 = partials + tile * 9;
        const float* p2 = partials + (81 + tile) * 9;
#pragma unroll
        for (int k = 0; k < 9; k++) w[k] += p1[k] + p2[k];
        // selection per candidate (dy,dx): window (ey(dy), ex(dx))
#pragma unroll
        for (int dy = 0; dy < 3; dy++) {
            int e = (dy == 0) ? 0 : ((dy == 1) ? ey1 : ey2);
            float a0 = (e == 0) ? w[0] : ((e == 1) ? w[3] : w[6]);
            float a1 = (e == 0) ? w[1] : ((e == 1) ? w[4] : w[7]);
            float a2 = (e == 0) ? w[2] : ((e == 1) ? w[5] : w[8]);
            float s0 = a0;
            float s1 = (ex1 == 0) ? a0 : ((ex1 == 1) ? a1 : a2);
            float s2 = (ex2 == 0) ? a0 : ((ex2 == 1) ? a1 : a2);
            int o = (oy0 + dy) * WSZ + ox0;
            sc[o] = s0; sc[o + 1] = s1; sc[o + 2] = s2;
            m3 = fmaxf(m3, fmaxf(s0, fmaxf(s1, s2)));
        }
    }
    // ---- exact block max ----
#pragma unroll
    for (int s = 16; s > 0; s >>= 1) m3 = fmaxf(m3, __shfl_xor_sync(0xffffffffu, m3, s));
    if (lane == 0) redf[w5] = m3;
    __syncthreads();
    float vmax = redf[0];
#pragma unroll
    for (int s = 1; s < 8; s++) vmax = fmaxf(vmax, redf[s]);
    float th = vmax - 12.0f;

    // ---- band compaction (warp 0); bandcnt>KSEL -> fallback sort ----
    if (tid < 32) {
        int cnt = 0;
        for (int base = 0; base < 736; base += 32) {
            int i = base + tid;
            bool f = (i < WSZ * WSZ) && (sc[i] >= th);
            unsigned m = __ballot_sync(0xffffffffu, f);
            int pos = cnt + __popc(m & ((1u << tid) - 1u));
            if (f && pos < KSEL) nzi[pos] = i;
            cnt += __popc(m);
        }
        if (tid == 0) *nzc = cnt;
    }
    __syncthreads();
    int bandcnt = *nzc;

    int nnz;
    float inv;
    if (bandcnt <= KSEL) {
        nnz = bandcnt;
        float e = 0.f;
        if (tid < nnz) {
            int csel = nzi[tid];
            int soy = csel / WSZ, sox = csel - soy * WSZ;
            int cy = min(max(qi + soy - 13, 0), H - 1);
            int cx = min(max(qj + sox - 13, 0), W - 1);
            cyx[tid] = (cy << 16) | cx;
            e = expf((sc[csel] - vmax) * 10.f);
            wgt[tid] = e;
        }
#pragma unroll
        for (int s = 16; s > 0; s >>= 1) e += __shfl_xor_sync(0xffffffffu, e, s);
        if (lane == 0) redf[w5] = e;
        __syncthreads();
        inv = 1.f / (redf[0] + redf[1] + redf[2] + redf[3]
                   + redf[4] + redf[5] + redf[6] + redf[7]);
        __syncthreads();
    } else {
        // ---- fallback: exact top-100 via full bitonic sort (rare) ----
        for (int i = tid; i < 1024; i += 256) {
            unsigned long long kk;
            if (i < WSZ * WSZ) {
                unsigned int b = __float_as_uint(sc[i]);
                unsigned int u = (b & 0x80000000u) ? ~b : (b | 0x80000000u);
                kk = (((unsigned long long)(~u)) << 32) | (unsigned int)i;
            } else {
                kk = 0xFFFFFFFFFFFFFFFFull;
            }
            keys[i] = kk;
        }
        __syncthreads();
#pragma unroll 1
        for (int k = 2; k <= 1024; k <<= 1) {
#pragma unroll 1
            for (int j = k >> 1; j > 0; j >>= 1) {
                if (j >= 128) {
                    __syncthreads();
                    for (int i = tid; i < 1024; i += 256) {
                        int ixj = i ^ j;
                        if (ixj > i) {
                            bool up = ((i & k) == 0);
                            unsigned long long a = keys[i], b = keys[ixj];
                            if ((a > b) == up) { keys[i] = b; keys[ixj] = a; }
                        }
                    }
                    __syncthreads();
                } else {
#pragma unroll
                    for (int n = 0; n < 4; n++) {
                        int i = (w5 << 7) + (n << 5) + lane;
                        int ixj = i ^ j;
                        if (ixj > i) {
                            bool up = ((i & k) == 0);
                            unsigned long long a = keys[i], b = keys[ixj];
                            if ((a > b) == up) { keys[i] = b; keys[ixj] = a; }
                        }
                    }
                    __syncwarp();
                }
            }
        }
        __syncthreads();
        nnz = KSEL;
        float e = 0.f;
        if (tid < KSEL) {
            int csel = (int)(keys[tid] & 0xFFFFFFFFull);
            int soy = csel / WSZ, sox = csel - soy * WSZ;
            int cy = min(max(qi + soy - 13, 0), H - 1);
            int cx = min(max(qj + sox - 13, 0), W - 1);
            cyx[tid] = (cy << 16) | cx;
            e = expf((sc[csel] - vmax) * 10.f);
            wgt[tid] = e;
        }
#pragma unroll
        for (int s = 16; s > 0; s >>= 1) e += __shfl_xor_sync(0xffffffffu, e, s);
        if (lane == 0) redf[w5] = e;
        __syncthreads();
        inv = 1.f / (redf[0] + redf[1] + redf[2] + redf[3]
                   + redf[4] + redf[5] + redf[6] + redf[7]);
        __syncthreads();
    }

    // ---- aggregation: 4 d's per thread, MLP-4 L2 loads from v2 ----
    const float* v2t = v2g + t * NCI * H * W;
    float* zp = zbuf + (t * NQ + q) * PD;
    if (tid < 196) {
        int d0 = tid * 4;
        int cb[4], piu[4], pju[4];
#pragma unroll
        for (int u = 0; u < 4; u++) {
            int d = d0 + u;
            int ci = d / 49, r = d - ci * 49;
            piu[u] = r / 7; pju[u] = r - piu[u] * 7;
            cb[u] = ci * (H * W);
        }
        float acc[4] = {0.f, 0.f, 0.f, 0.f};
#pragma unroll 1
        for (int m = 0; m < nnz; m++) {
            float wv = wgt[m];
            if (wv == 0.f) continue;
            int p = cyx[m];
            int cy = p >> 16, cx = p & 0xFFFF;
#pragma unroll
            for (int u = 0; u < 4; u++) {
                int ryv = min(cy + piu[u], H - 1);
                int rxv = min(cx + pju[u], W - 1);
                acc[u] += wv * v2t[cb[u] + ryv * W + rxv];
            }
        }
#pragma unroll
        for (int u = 0; u < 4; u++) zp[d0 + u] = acc[u] * inv;
    }
}

// ---------------------------------------------------------------------------
// Kernel 3: deterministic overlap-add gather + normalize by Zc
// ---------------------------------------------------------------------------
__global__ void __launch_bounds__(256) final_kernel(float* __restrict__ out)
{
    int idx = blockIdx.x * 256 + threadIdx.x;
    if (idx >= T * NCI * H * W) return;
    int x = idx & 127;
    int y = (idx >> 7) & 127;
    int ci = (idx >> 14) & 15;
    int t = idx >> 18;

    int ai[4], api[4], ni = 0;
    if (y == 127) {
        ai[0] = ai[1] = ai[2] = ai[3] = 31;
        api[0] = 3; api[1] = 4; api[2] = 5; api[3] = 6; ni = 4;
    } else {
        for (int p = (y & 3); p < 7; p += 4) {
            int a = (y - p) >> 2;
            if (y - p >= 0) { ai[ni] = a; api[ni] = p; ni++; }
        }
    }
    int aj[4], apj[4], nj = 0;
    if (x == 127) {
        aj[0] = aj[1] = aj[2] = aj[3] = 31;
        apj[0] = 3; apj[1] = 4; apj[2] = 5; apj[3] = 6; nj = 4;
    } else {
        for (int p = (x & 3); p < 7; p += 4) {
            int a = (x - p) >> 2;
            if (x - p >= 0) { aj[nj] = a; apj[nj] = p; nj++; }
        }
    }

    float acc = 0.f;
    for (int u = 0; u < ni; u++) {
        for (int v = 0; v < nj; v++) {
            int qq = ai[u] * 32 + aj[v];
            int d = ci * 49 + api[u] * 7 + apj[v];
            acc += zbuf[((t << 10) + qq) * PD + d];
        }
    }
    out[idx] = acc / (float)(ni * nj);
}

// ---------------------------------------------------------------------------
extern "C" void kernel_launch(void* const* d_in, const int* in_sizes, int n_in,
                              void* d_out, int out_size)
{
    const float* vid = (const float*)d_in[0];
    const float* gw  = (const float*)d_in[1];
    const float* gb  = (const float*)d_in[2];
    const float* thw = (const float*)d_in[3];
    const float* thb = (const float*)d_in[4];
    float* out = (float*)d_out;

    int conv_sm = (9216 + 1024 + 1440) * 4;   // 46720 B
    int main_sm = SMF * 4;                     // 39588 B
    cudaFuncSetAttribute(conv_kernel, cudaFuncAttributeMaxDynamicSharedMemorySize, conv_sm);
    cudaFuncSetAttribute(main_kernel, cudaFuncAttributeMaxDynamicSharedMemorySize, main_sm);

    nudge_kernel<<<1, 32>>>();                                   // idx 0 (mod 6)
    conv_kernel<<<dim3(128, T), 128, conv_sm>>>(vid, gw, gb, thw, thb);  // idx 1
    nudge_kernel<<<1, 32>>>();                                   // idx 2
    main_kernel<<<dim3(NQ, T), 256, main_sm>>>();                // idx 3  <- ncu slot 15
    int ntot = T * NCI * H * W;
    final_kernel<<<(ntot + 255) / 256, 256>>>(out);              // idx 4
    nudge_kernel<<<1, 32>>>();                                   // idx 5
}

// round 15
// speedup vs baseline: 1.2671x; 1.1643x over previous
#include <cuda_runtime.h>

#define T 4
#define H 128
#define W 128
#define NCI 16
#define NCIN 64
#define PS 7
#define WSZ 27
#define NQ 1024
#define KSEL 100
#define PITCH2 39
#define CHSZ 1521   // 39*39 (pitch layout; only 33x33 extent is staged/used)
#define PD 784      // NCI*PS*PS

__device__ float v1g[T * NCI * H * W];
__device__ float v2g[T * NCI * H * W];
__device__ float zbuf[T * NQ * PD];

// ---------------------------------------------------------------------------
// Kernel 0: no-op (capture-slot alignment: index 15 -> main_kernel)
// ---------------------------------------------------------------------------
__global__ void nudge_kernel() {}

// ---------------------------------------------------------------------------
// Kernel 1: fused 3x3 conv (v1) + 1x1 conv (v2), 64ch -> 16ch
// ---------------------------------------------------------------------------
__global__ void __launch_bounds__(128) conv_kernel(
    const float* __restrict__ vid, const float* __restrict__ gw,
    const float* __restrict__ gb, const float* __restrict__ thw,
    const float* __restrict__ thb)
{
    extern __shared__ float sm[];
    float* wsm  = sm;              // [64][9][16] = 9216 f
    float* thsm = sm + 9216;       // [64][16]    = 1024 f
    float* tsm  = sm + 10240;      // [8][18][10] = 1440 f

    int tid = threadIdx.x;
    int t = blockIdx.y;
    int bx = blockIdx.x;
    int ty0 = (bx >> 4) * 16, tx0 = (bx & 15) * 8;

    for (int n = tid; n < NCI * NCIN * 9; n += 128) {
        int co = n / 576, r = n - co * 576;
        int cin = r / 9, k = r - cin * 9;
        wsm[(cin * 9 + k) * 16 + co] = gw[n];
    }
    for (int n = tid; n < NCI * NCIN; n += 128) {
        int co = n >> 6, cin = n & 63;
        thsm[cin * 16 + co] = thw[co * 64 + cin];
    }

    float acc1[16], acc2[16];
#pragma unroll
    for (int i = 0; i < 16; i++) { acc1[i] = 0.f; acc2[i] = 0.f; }

    int py = tid >> 3, px = tid & 7;
    int gy = ty0 + py, gx = tx0 + px;

    for (int c0 = 0; c0 < NCIN; c0 += 8) {
        __syncthreads();
        for (int n = tid; n < 8 * 18 * 10; n += 128) {
            int cc = n / 180, r = n - cc * 180;
            int yy = r / 10, xx = r - yy * 10;
            int iy = ty0 + yy - 1, ix = tx0 + xx - 1;
            float v = 0.f;
            if (iy >= 0 && iy < H && ix >= 0 && ix < W)
                v = vid[((t * NCIN + c0 + cc) * H + iy) * W + ix];
            tsm[n] = v;
        }
        __syncthreads();
#pragma unroll
        for (int cc = 0; cc < 8; cc++) {
            const float* tp = &tsm[cc * 180 + py * 10 + px];
            float v[9];
            v[0] = tp[0];  v[1] = tp[1];  v[2] = tp[2];
            v[3] = tp[10]; v[4] = tp[11]; v[5] = tp[12];
            v[6] = tp[20]; v[7] = tp[21]; v[8] = tp[22];
            const float4* wp = reinterpret_cast<const float4*>(&wsm[(c0 + cc) * 144]);
#pragma unroll
            for (int k = 0; k < 9; k++) {
                float vv = v[k];
#pragma unroll
                for (int q4 = 0; q4 < 4; q4++) {
                    float4 w4 = wp[k * 4 + q4];
                    acc1[q4 * 4 + 0] += vv * w4.x;
                    acc1[q4 * 4 + 1] += vv * w4.y;
                    acc1[q4 * 4 + 2] += vv * w4.z;
                    acc1[q4 * 4 + 3] += vv * w4.w;
                }
            }
            float vc = v[4];
            const float4* tp4 = reinterpret_cast<const float4*>(&thsm[(c0 + cc) * 16]);
#pragma unroll
            for (int q4 = 0; q4 < 4; q4++) {
                float4 w4 = tp4[q4];
                acc2[q4 * 4 + 0] += vc * w4.x;
                acc2[q4 * 4 + 1] += vc * w4.y;
                acc2[q4 * 4 + 2] += vc * w4.z;
                acc2[q4 * 4 + 3] += vc * w4.w;
            }
        }
    }
#pragma unroll
    for (int co = 0; co < 16; co++) {
        int oidx = ((t * NCI + co) * H + gy) * W + gx;
        v1g[oidx] = acc1[co] + gb[co];
        v2g[oidx] = acc2[co] + thb[co];
    }
}

// ---------------------------------------------------------------------------
// Kernel 2: 3x3 candidate tiles x 3 channel-slices, clamped staging at
// pitch 39 (conflict-free score loop), staged extent trimmed to the 33x33
// actually read. Band select (sort-free common path, bitonic fallback).
// smem (floats): reg 0..12168 | qp 12168..12624 | sc 12624..13360
// aliases after score: partials+keys over reg; wgt/... over qp.
// ---------------------------------------------------------------------------
#define SMF 13360

__device__ __forceinline__ void stage8c(
    const float* __restrict__ src, float* __restrict__ reg,
    int r0, int c0, int w5, int lane)
{
    int xs1 = min(c0 + lane, 127);
    int xs2 = min(c0 + 32, 127);
#pragma unroll
    for (int ci = 0; ci < 8; ci++) {
        const float* sbase = src + ci * (H * W);
        float* dbase = reg + ci * CHSZ;
#pragma unroll 2
        for (int y = w5; y < 33; y += 8) {
            const float* srow = sbase + min(r0 + y, 127) * W;
            float* drow = dbase + y * PITCH2;
            drow[lane] = srow[xs1];
            if (lane == 0) drow[32] = srow[xs2];
        }
    }
}

__global__ void __launch_bounds__(256, 4) main_kernel()
{
    extern __shared__ float sm[];
    float* reg = sm;
    float* qp  = sm + 12168;
    float* sc  = sm + 12624;
    // aliases (live only after score phase):
    float* partials = sm;                                 // [2][81][9] over reg
    unsigned long long* keys = (unsigned long long*)sm;   // fallback only
    float* wgt  = qp;                                     // 100
    int*   cyx  = (int*)(qp + 100);                       // 100 (abs cy<<16|cx)
    float* redf = qp + 200;                               // 8
    int*   nzc  = (int*)(qp + 216);                       // 1
    int*   nzi  = (int*)(qp + 220);                       // 100

    int tid = threadIdx.x;
    int w5 = tid >> 5, lane = tid & 31;
    int q = blockIdx.x, t = blockIdx.y;
    int qi = (q >> 5) << 2, qj = (q & 31) << 2;
    int r0 = max(qi - 13, 0);
    int c0 = max(qj - 13, 0);

    // thread -> (channel slice, 3x3 candidate tile)
    bool act = tid < 243;
    int slice = 0, tile = 0;
    if (act) { slice = tid / 81; tile = tid - slice * 81; }
    int ty = tile % 9, tx = tile / 9;
    int oy0 = ty * 3, ox0 = tx * 3;
    // clamped anchors (upper clamp baked into staging; lower via e-offsets)
    int ay0 = max(qi + oy0 - 13 - r0, 0);
    int ax0 = max(qj + ox0 - 13 - c0, 0);
    int ey1 = max(qi + oy0 - 12 - r0, 0) - ay0;
    int ey2 = max(qi + oy0 - 11 - r0, 0) - ay0;
    int ex1 = max(qj + ox0 - 12 - c0, 0) - ax0;
    int ex2 = max(qj + ox0 - 11 - c0, 0) - ax0;
    int cs = slice * 3;
    int ce = (slice == 2) ? 8 : cs + 3;

    float w[9];
#pragma unroll
    for (int k = 0; k < 9; k++) w[k] = 0.f;

#pragma unroll 1
    for (int pass = 0; pass < 2; pass++) {
        stage8c(v1g + (t * NCI + pass * 8) * H * W, reg, r0, c0, w5, lane);
        __syncthreads();

        // query patch (clamps baked into staging; direct copy), rows padded to 8
        if (tid < 196) {
            for (int d = tid; d < 392; d += 196) {
                int ci = d / 49, r = d - ci * 49, pi = r / 7, pj = r - pi * 7;
                qp[(ci * 7 + pi) * 8 + pj] =
                    reg[ci * CHSZ + (qi - r0 + pi) * PITCH2 + (qj - c0 + pj)];
            }
        } else if (tid < 252) {
            qp[(tid - 196) * 8 + 7] = 0.f;
        }
        __syncthreads();

        if (act) {
#pragma unroll 1
            for (int ci = cs; ci < ce; ci++) {
                const float* base = reg + ci * CHSZ + ay0 * PITCH2 + ax0;
                const float4* qv = reinterpret_cast<const float4*>(qp) + ci * 14;
#pragma unroll
                for (int r = 0; r < 9; r++) {
                    const float* row = base + r * PITCH2;
                    float v0 = row[0], v1 = row[1], v2 = row[2], v3 = row[3];
                    float v4 = row[4], v5 = row[5], v6 = row[6], v7 = row[7];
                    float v8 = row[8];
#pragma unroll
                    for (int e = 0; e < 3; e++) {
                        int pi = r - e;
                        if (pi >= 0 && pi < 7) {
                            float4 a = qv[2 * pi], b = qv[2 * pi + 1];
                            w[e * 3 + 0] += a.x * v0 + a.y * v1 + a.z * v2 + a.w * v3
                                          + b.x * v4 + b.y * v5 + b.z * v6;
                            w[e * 3 + 1] += a.x * v1 + a.y * v2 + a.z * v3 + a.w * v4
                                          + b.x * v5 + b.y * v6 + b.z * v7;
                            w[e * 3 + 2] += a.x * v2 + a.y * v3 + a.z * v4 + a.w * v5
                                          + b.x * v6 + b.y * v7 + b.z * v8;
                        }
                    }
                }
            }
        }
        __syncthreads();   // before restage / partial writes overwrite reg
    }

    // ---- cross-slice reduction via reg alias ----
    if (act && slice > 0) {
        float* pp = partials + ((slice - 1) * 81 + tile) * 9;
#pragma unroll
        for (int k = 0; k < 9; k++) pp[k] = w[k];
    }
    __syncthreads();
    float m3 = -3.4e38f;
    if (tid < 81) {
        const float* p1 = partials + tile * 9;
        const float* p2 = partials + (81 + tile) * 9;
#pragma unroll
        for (int k = 0; k < 9; k++) w[k] += p1[k] + p2[k];
        // selection per candidate (dy,dx): window (ey(dy), ex(dx))
#pragma unroll
        for (int dy = 0; dy < 3; dy++) {
            int e = (dy == 0) ? 0 : ((dy == 1) ? ey1 : ey2);
            float a0 = (e == 0) ? w[0] : ((e == 1) ? w[3] : w[6]);
            float a1 = (e == 0) ? w[1] : ((e == 1) ? w[4] : w[7]);
            float a2 = (e == 0) ? w[2] : ((e == 1) ? w[5] : w[8]);
            float s0 = a0;
            float s1 = (ex1 == 0) ? a0 : ((ex1 == 1) ? a1 : a2);
            float s2 = (ex2 == 0) ? a0 : ((ex2 == 1) ? a1 : a2);
            int o = (oy0 + dy) * WSZ + ox0;
            sc[o] = s0; sc[o + 1] = s1; sc[o + 2] = s2;
            m3 = fmaxf(m3, fmaxf(s0, fmaxf(s1, s2)));
        }
    }
    // ---- exact block max ----
#pragma unroll
    for (int s = 16; s > 0; s >>= 1) m3 = fmaxf(m3, __shfl_xor_sync(0xffffffffu, m3, s));
    if (lane == 0) redf[w5] = m3;
    __syncthreads();
    float vmax = redf[0];
#pragma unroll
    for (int s = 1; s < 8; s++) vmax = fmaxf(vmax, redf[s]);
    float th = vmax - 12.0f;

    // ---- band compaction (warp 0); bandcnt>KSEL -> fallback sort ----
    if (tid < 32) {
        int cnt = 0;
        for (int base = 0; base < 736; base += 32) {
            int i = base + tid;
            bool f = (i < WSZ * WSZ) && (sc[i] >= th);
            unsigned m = __ballot_sync(0xffffffffu, f);
            int pos = cnt + __popc(m & ((1u << tid) - 1u));
            if (f && pos < KSEL) nzi[pos] = i;
            cnt += __popc(m);
        }
        if (tid == 0) *nzc = cnt;
    }
    __syncthreads();
    int bandcnt = *nzc;

    int nnz;
    float inv;
    if (bandcnt <= KSEL) {
        nnz = bandcnt;
        float e = 0.f;
        if (tid < nnz) {
            int csel = nzi[tid];
            int soy = csel / WSZ, sox = csel - soy * WSZ;
            int cy = min(max(qi + soy - 13, 0), H - 1);
            int cx = min(max(qj + sox - 13, 0), W - 1);
            cyx[tid] = (cy << 16) | cx;
            e = expf((sc[csel] - vmax) * 10.f);
            wgt[tid] = e;
        }
#pragma unroll
        for (int s = 16; s > 0; s >>= 1) e += __shfl_xor_sync(0xffffffffu, e, s);
        if (lane == 0) redf[w5] = e;
        __syncthreads();
        inv = 1.f / (redf[0] + redf[1] + redf[2] + redf[3]
                   + redf[4] + redf[5] + redf[6] + redf[7]);
        __syncthreads();
    } else {
        // ---- fallback: exact top-100 via full bitonic sort (rare) ----
        for (int i = tid; i < 1024; i += 256) {
            unsigned long long kk;
            if (i < WSZ * WSZ) {
                unsigned int b = __float_as_uint(sc[i]);
                unsigned int u = (b & 0x80000000u) ? ~b : (b | 0x80000000u);
                kk = (((unsigned long long)(~u)) << 32) | (unsigned int)i;
            } else {
                kk = 0xFFFFFFFFFFFFFFFFull;
            }
            keys[i] = kk;
        }
        __syncthreads();
#pragma unroll 1
        for (int k = 2; k <= 1024; k <<= 1) {
#pragma unroll 1
            for (int j = k >> 1; j > 0; j >>= 1) {
                if (j >= 128) {
                    __syncthreads();
                    for (int i = tid; i < 1024; i += 256) {
                        int ixj = i ^ j;
                        if (ixj > i) {
                            bool up = ((i & k) == 0);
                            unsigned long long a = keys[i], b = keys[ixj];
                            if ((a > b) == up) { keys[i] = b; keys[ixj] = a; }
                        }
                    }
                    __syncthreads();
                } else {
#pragma unroll
                    for (int n = 0; n < 4; n++) {
                        int i = (w5 << 7) + (n << 5) + lane;
                        int ixj = i ^ j;
                        if (ixj > i) {
                            bool up = ((i & k) == 0);
                            unsigned long long a = keys[i], b = keys[ixj];
                            if ((a > b) == up) { keys[i] = b; keys[ixj] = a; }
                        }
                    }
                    __syncwarp();
                }
            }
        }
        __syncthreads();
        nnz = KSEL;
        float e = 0.f;
        if (tid < KSEL) {
            int csel = (int)(keys[tid] & 0xFFFFFFFFull);
            int soy = csel / WSZ, sox = csel - soy * WSZ;
            int cy = min(max(qi + soy - 13, 0), H - 1);
            int cx = min(max(qj + sox - 13, 0), W - 1);
            cyx[tid] = (cy << 16) | cx;
            e = expf((sc[csel] - vmax) * 10.f);
            wgt[tid] = e;
        }
#pragma unroll
        for (int s = 16; s > 0; s >>= 1) e += __shfl_xor_sync(0xffffffffu, e, s);
        if (lane == 0) redf[w5] = e;
        __syncthreads();
        inv = 1.f / (redf[0] + redf[1] + redf[2] + redf[3]
                   + redf[4] + redf[5] + redf[6] + redf[7]);
        __syncthreads();
    }

    // ---- aggregation: 4 d's per thread, MLP-4 L2 loads from v2 ----
    const float* v2t = v2g + t * NCI * H * W;
    float* zp = zbuf + (t * NQ + q) * PD;
    if (tid < 196) {
        int d0 = tid * 4;
        int cb[4], piu[4], pju[4];
#pragma unroll
        for (int u = 0; u < 4; u++) {
            int d = d0 + u;
            int ci = d / 49, r = d - ci * 49;
            piu[u] = r / 7; pju[u] = r - piu[u] * 7;
            cb[u] = ci * (H * W);
        }
        float acc[4] = {0.f, 0.f, 0.f, 0.f};
#pragma unroll 1
        for (int m = 0; m < nnz; m++) {
            float wv = wgt[m];
            if (wv == 0.f) continue;
            int p = cyx[m];
            int cy = p >> 16, cx = p & 0xFFFF;
#pragma unroll
            for (int u = 0; u < 4; u++) {
                int ryv = min(cy + piu[u], H - 1);
                int rxv = min(cx + pju[u], W - 1);
                acc[u] += wv * v2t[cb[u] + ryv * W + rxv];
            }
        }
#pragma unroll
        for (int u = 0; u < 4; u++) zp[d0 + u] = acc[u] * inv;
    }
}

// ---------------------------------------------------------------------------
// Kernel 3: deterministic overlap-add gather + normalize by Zc
// ---------------------------------------------------------------------------
__global__ void __launch_bounds__(256) final_kernel(float* __restrict__ out)
{
    int idx = blockIdx.x * 256 + threadIdx.x;
    if (idx >= T * NCI * H * W) return;
    int x = idx & 127;
    int y = (idx >> 7) & 127;
    int ci = (idx >> 14) & 15;
    int t = idx >> 18;

    int ai[4], api[4], ni = 0;
    if (y == 127) {
        ai[0] = ai[1] = ai[2] = ai[3] = 31;
        api[0] = 3; api[1] = 4; api[2] = 5; api[3] = 6; ni = 4;
    } else {
        for (int p = (y & 3); p < 7; p += 4) {
            int a = (y - p) >> 2;
            if (y - p >= 0) { ai[ni] = a; api[ni] = p; ni++; }
        }
    }
    int aj[4], apj[4], nj = 0;
    if (x == 127) {
        aj[0] = aj[1] = aj[2] = aj[3] = 31;
        apj[0] = 3; apj[1] = 4; apj[2] = 5; apj[3] = 6; nj = 4;
    } else {
        for (int p = (x & 3); p < 7; p += 4) {
            int a = (x - p) >> 2;
            if (x - p >= 0) { aj[nj] = a; apj[nj] = p; nj++; }
        }
    }

    float acc = 0.f;
    for (int u = 0; u < ni; u++) {
        for (int v = 0; v < nj; v++) {
            int qq = ai[u] * 32 + aj[v];
            int d = ci * 49 + api[u] * 7 + apj[v];
            acc += zbuf[((t << 10) + qq) * PD + d];
        }
    }
    out[idx] = acc / (float)(ni * nj);
}

// ---------------------------------------------------------------------------
extern "C" void kernel_launch(void* const* d_in, const int* in_sizes, int n_in,
                              void* d_out, int out_size)
{
    const float* vid = (const float*)d_in[0];
    const float* gw  = (const float*)d_in[1];
    const float* gb  = (const float*)d_in[2];
    const float* thw = (const float*)d_in[3];
    const float* thb = (const float*)d_in[4];
    float* out = (float*)d_out;

    int conv_sm = (9216 + 1024 + 1440) * 4;   // 46720 B
    int main_sm = SMF * 4;                     // 53440 B
    cudaFuncSetAttribute(conv_kernel, cudaFuncAttributeMaxDynamicSharedMemorySize, conv_sm);
    cudaFuncSetAttribute(main_kernel, cudaFuncAttributeMaxDynamicSharedMemorySize, main_sm);

    nudge_kernel<<<1, 32>>>();                                   // idx 0 (mod 6)
    conv_kernel<<<dim3(128, T), 128, conv_sm>>>(vid, gw, gb, thw, thb);  // idx 1
    nudge_kernel<<<1, 32>>>();                                   // idx 2
    main_kernel<<<dim3(NQ, T), 256, main_sm>>>();                // idx 3  <- ncu slot 15
    int ntot = T * NCI * H * W;
    final_kernel<<<(ntot + 255) / 256, 256>>>(out);              // idx 4
    nudge_kernel<<<1, 32>>>();                                   // idx 5
}